// round 8
// baseline (speedup 1.0000x reference)
#include <cuda_runtime.h>

typedef unsigned long long u64;
#define NFFT 1024
#define TWO_PI 6.2831853071795864769f

// ---- packed f32x2 helpers (sm_103a) ----
__device__ __forceinline__ u64 pk(float x, float y) {
    u64 u; asm("mov.b64 %0,{%1,%2};" : "=l"(u) : "f"(x), "f"(y)); return u;
}
__device__ __forceinline__ void upk(u64 u, float& x, float& y) {
    asm("mov.b64 {%0,%1},%2;" : "=f"(x), "=f"(y) : "l"(u));
}
__device__ __forceinline__ u64 padd(u64 a, u64 b) {
    u64 d; asm("add.rn.f32x2 %0,%1,%2;" : "=l"(d) : "l"(a), "l"(b)); return d;
}
__device__ __forceinline__ u64 pmul(u64 a, u64 b) {
    u64 d; asm("mul.rn.f32x2 %0,%1,%2;" : "=l"(d) : "l"(a), "l"(b)); return d;
}
__device__ __forceinline__ u64 pfma(u64 a, u64 b, u64 c) {
    u64 d; asm("fma.rn.f32x2 %0,%1,%2,%3;" : "=l"(d) : "l"(a), "l"(b), "l"(c)); return d;
}
__device__ __forceinline__ u64 psub(u64 a, u64 b) {  // a - b
    const u64 NEG1 = 0xBF800000BF800000ULL;
    return pfma(b, NEG1, a);
}
__device__ __forceinline__ u64 cmulc(u64 a, float br, float bi) {
    float ar, ai; upk(a, ar, ai);
    return pk(fmaf(-ai, bi, ar * br), fmaf(ar, bi, ai * br));
}
__device__ __forceinline__ u64 muli(u64 a) {  // a * i
    float ar, ai; upk(a, ar, ai);
    return pk(-ai, ar);
}

// Inverse (sign = +i) radix-4 butterfly on packed complex values.
__device__ __forceinline__ void bfly4_inv(u64 v[4]) {
    u64 t0 = padd(v[0], v[2]);
    u64 t1 = psub(v[0], v[2]);
    u64 t2 = padd(v[1], v[3]);
    u64 t3 = psub(v[1], v[3]);
    v[0] = padd(t0, t2);
    v[2] = psub(t0, t2);
    u64 w = muli(t3);
    v[1] = padd(t1, w);
    v[3] = psub(t1, w);
}

// In-register inverse 16-point DFT, natural order in and out.
__device__ __forceinline__ void dft16_inv(u64 v[16]) {
    const float C  = 0.70710678118654752f;   // cos(pi/4)
    const float C1 = 0.92387953251128676f;   // cos(pi/8)
    const float S1 = 0.38268343236508977f;   // sin(pi/8)
    u64 a[16];  // a[k1*4 + n2]
#pragma unroll
    for (int n2 = 0; n2 < 4; ++n2) {
        u64 t[4] = { v[n2], v[n2 + 4], v[n2 + 8], v[n2 + 12] };
        bfly4_inv(t);
        a[0 + n2] = t[0]; a[4 + n2] = t[1]; a[8 + n2] = t[2]; a[12 + n2] = t[3];
    }
    a[4 + 1]  = cmulc(a[4 + 1],  C1,  S1);
    a[4 + 2]  = cmulc(a[4 + 2],  C,   C);
    a[4 + 3]  = cmulc(a[4 + 3],  S1,  C1);
    a[8 + 1]  = cmulc(a[8 + 1],  C,   C);
    a[8 + 2]  = muli (a[8 + 2]);
    a[8 + 3]  = cmulc(a[8 + 3], -C,   C);
    a[12 + 1] = cmulc(a[12 + 1],  S1,  C1);
    a[12 + 2] = cmulc(a[12 + 2], -C,   C);
    a[12 + 3] = cmulc(a[12 + 3], -C1, -S1);
#pragma unroll
    for (int k1 = 0; k1 < 4; ++k1) {
        u64 t[4] = { a[k1 * 4 + 0], a[k1 * 4 + 1], a[k1 * 4 + 2], a[k1 * 4 + 3] };
        bfly4_inv(t);
        v[k1] = t[0]; v[k1 + 4] = t[1]; v[k1 + 8] = t[2]; v[k1 + 12] = t[3];
    }
}

// Persistent-CTA 1024-pt inverse FFT with SOFTWARE-PIPELINED global loads:
// the next row-pair's 32 LDGs are issued in the register hole where v[16]
// is dead (between exchange-2 stores and Phase C), so the DRAM pipe stays
// fed across iteration boundaries. Body otherwise identical to R6.
__global__ void __launch_bounds__(128, 8)
ifft1024_kernel(const float* __restrict__ gre, const float* __restrict__ gim,
                float* __restrict__ outr, float* __restrict__ outi,
                int nrp)
{
    __shared__ u64 sh[2][NFFT];
    const int tid = threadIdx.x;
    const int rowl = tid >> 6;
    const int t = tid & 63;
    u64* s = sh[rowl];
    const int stride = gridDim.x;

    u64 v[16];

    int rp = blockIdx.x;
    size_t base = ((size_t)rp * 2 + rowl) * NFFT;

    // ---- prologue: load first row-pair ----
#pragma unroll
    for (int n1 = 0; n1 < 16; ++n1)
        v[n1] = pk(gre[base + 64 * n1 + t], gim[base + 64 * n1 + t]);

    for (; rp < nrp; rp += stride) {
        // ---- Phase A: DFT16 over n1 (stride 64), twiddle W1024^(t*k1) ----
        dft16_inv(v);
        {
            const float ang = (TWO_PI / 1024.0f) * (float)t;
#pragma unroll
            for (int k1 = 1; k1 < 16; ++k1) {
                float sn, cs;
                __sincosf(ang * (float)k1, &sn, &cs);
                v[k1] = cmulc(v[k1], cs, sn);
            }
            const int hi = (t >> 4) << 8;
            const int lo = t & 15;
#pragma unroll
            for (int k1 = 0; k1 < 16; ++k1)
                s[hi | (k1 << 4) | (lo ^ ((k1 & 3) << 2))] = v[k1];
        }
        __syncthreads();

        // ---- Phase B: DFT16 over m (n2 = 4m+q), twiddle W64^(q*c) ----
        {
            const int k1 = t >> 2, q = t & 3;
#pragma unroll
            for (int m = 0; m < 16; ++m) {
                const int n2 = 4 * m + q;
                const int phys = ((n2 >> 4) << 8) | (k1 << 4) | ((n2 & 15) ^ ((k1 & 3) << 2));
                v[m] = s[phys];
            }
            dft16_inv(v);
            const float ang = (TWO_PI / 64.0f) * (float)q;
#pragma unroll
            for (int c = 1; c < 16; ++c) {
                float sn, cs;
                __sincosf(ang * (float)c, &sn, &cs);
                v[c] = cmulc(v[c], cs, sn);
            }
            __syncthreads();   // all reads of exchange-1 complete before reuse
#pragma unroll
            for (int c = 0; c < 16; ++c) {
                const int idx = k1 + 16 * c + 256 * q;
                s[idx ^ (q << 2)] = v[c];
            }
        }

        // ---- prefetch next row-pair into v (v is dead here) ----
        // Clamped on the last iteration (harmless valid reload).
        {
            const int rpn = (rp + stride < nrp) ? (rp + stride) : rp;
            const size_t nbase = ((size_t)rpn * 2 + rowl) * NFFT;
#pragma unroll
            for (int n1 = 0; n1 < 16; ++n1)
                v[n1] = pk(gre[nbase + 64 * n1 + t], gim[nbase + 64 * n1 + t]);
        }
        __syncthreads();

        // ---- Phase C: final radix-4 across q, coalesced stores ----
        {
            const u64 SC = 0x3A8000003A800000ULL;   // packed (1/1024, 1/1024)
#pragma unroll
            for (int jj = 0; jj < 4; ++jj) {
                const int p = t + 64 * jj;     // p = k1 + 16*c in [0,256)
                u64 u[4];
#pragma unroll
                for (int q = 0; q < 4; ++q) {
                    const int idx = p + 256 * q;
                    u[q] = s[idx ^ (q << 2)];
                }
                bfly4_inv(u);
#pragma unroll
                for (int d = 0; d < 4; ++d) {
                    u64 y = pmul(u[d], SC);
                    float yr, yi; upk(y, yr, yi);
                    outr[base + p + 256 * d] = yr;
                    outi[base + p + 256 * d] = yi;
                }
            }
        }
        base = ((size_t)(rp + stride) * 2 + rowl) * NFFT;
        __syncthreads();   // Phase C reads done before next exchange-1 stores
    }
}

extern "C" void kernel_launch(void* const* d_in, const int* in_sizes, int n_in,
                              void* d_out, int out_size) {
    const float* re = (const float*)d_in[0];
    const float* im = (const float*)d_in[1];
    float* out = (float*)d_out;
    const int half = out_size / 2;           // y_real then y_imag, concatenated
    const int nrows = in_sizes[0] / NFFT;    // 32768
    const int nrp = nrows / 2;               // 16384 row-pairs

    const int GRID = 148 * 8;                // one full resident wave, persistent
    ifft1024_kernel<<<GRID, 128>>>(re, im, out, out + half, nrp);
}

// round 9
// speedup vs baseline: 1.1379x; 1.1379x over previous
#include <cuda_runtime.h>

typedef unsigned long long u64;
#define NFFT 1024
#define TWO_PI 6.2831853071795864769f

// ---- packed f32x2 helpers (sm_103a) ----
__device__ __forceinline__ u64 pk(float x, float y) {
    u64 u; asm("mov.b64 %0,{%1,%2};" : "=l"(u) : "f"(x), "f"(y)); return u;
}
__device__ __forceinline__ void upk(u64 u, float& x, float& y) {
    asm("mov.b64 {%0,%1},%2;" : "=f"(x), "=f"(y) : "l"(u));
}
__device__ __forceinline__ u64 padd(u64 a, u64 b) {
    u64 d; asm("add.rn.f32x2 %0,%1,%2;" : "=l"(d) : "l"(a), "l"(b)); return d;
}
__device__ __forceinline__ u64 pmul(u64 a, u64 b) {
    u64 d; asm("mul.rn.f32x2 %0,%1,%2;" : "=l"(d) : "l"(a), "l"(b)); return d;
}
__device__ __forceinline__ u64 pfma(u64 a, u64 b, u64 c) {
    u64 d; asm("fma.rn.f32x2 %0,%1,%2,%3;" : "=l"(d) : "l"(a), "l"(b), "l"(c)); return d;
}
__device__ __forceinline__ u64 psub(u64 a, u64 b) {  // a - b
    const u64 NEG1 = 0xBF800000BF800000ULL;
    return pfma(b, NEG1, a);
}
__device__ __forceinline__ u64 cmulc(u64 a, float br, float bi) {
    float ar, ai; upk(a, ar, ai);
    return pk(fmaf(-ai, bi, ar * br), fmaf(ar, bi, ai * br));
}
__device__ __forceinline__ u64 muli(u64 a) {  // a * i
    float ar, ai; upk(a, ar, ai);
    return pk(-ai, ar);
}

// Inverse (sign = +i) radix-4 butterfly on packed complex values.
__device__ __forceinline__ void bfly4_inv(u64 v[4]) {
    u64 t0 = padd(v[0], v[2]);
    u64 t1 = psub(v[0], v[2]);
    u64 t2 = padd(v[1], v[3]);
    u64 t3 = psub(v[1], v[3]);
    v[0] = padd(t0, t2);
    v[2] = psub(t0, t2);
    u64 w = muli(t3);
    v[1] = padd(t1, w);
    v[3] = psub(t1, w);
}

// In-register inverse 16-point DFT, natural order in and out.
__device__ __forceinline__ void dft16_inv(u64 v[16]) {
    const float C  = 0.70710678118654752f;   // cos(pi/4)
    const float C1 = 0.92387953251128676f;   // cos(pi/8)
    const float S1 = 0.38268343236508977f;   // sin(pi/8)
    u64 a[16];  // a[k1*4 + n2]
#pragma unroll
    for (int n2 = 0; n2 < 4; ++n2) {
        u64 t[4] = { v[n2], v[n2 + 4], v[n2 + 8], v[n2 + 12] };
        bfly4_inv(t);
        a[0 + n2] = t[0]; a[4 + n2] = t[1]; a[8 + n2] = t[2]; a[12 + n2] = t[3];
    }
    a[4 + 1]  = cmulc(a[4 + 1],  C1,  S1);
    a[4 + 2]  = cmulc(a[4 + 2],  C,   C);
    a[4 + 3]  = cmulc(a[4 + 3],  S1,  C1);
    a[8 + 1]  = cmulc(a[8 + 1],  C,   C);
    a[8 + 2]  = muli (a[8 + 2]);
    a[8 + 3]  = cmulc(a[8 + 3], -C,   C);
    a[12 + 1] = cmulc(a[12 + 1],  S1,  C1);
    a[12 + 2] = cmulc(a[12 + 2], -C,   C);
    a[12 + 3] = cmulc(a[12 + 3], -C1, -S1);
#pragma unroll
    for (int k1 = 0; k1 < 4; ++k1) {
        u64 t[4] = { a[k1 * 4 + 0], a[k1 * 4 + 1], a[k1 * 4 + 2], a[k1 * 4 + 3] };
        bfly4_inv(t);
        v[k1] = t[0]; v[k1 + 4] = t[1]; v[k1 + 8] = t[2]; v[k1 + 12] = t[3];
    }
}

// 1024-pt inverse FFT, ONE row per 64-thread CTA (R6 body, CTA split in half).
// Same 1024 threads/SM (64-reg cap), but 16 independently-scheduled CTAs/SM
// instead of 8: load bursts desynchronize, barriers couple only 2 warps.
__global__ void __launch_bounds__(64, 16)
ifft1024_kernel(const float* __restrict__ gre, const float* __restrict__ gim,
                float* __restrict__ outr, float* __restrict__ outi)
{
    __shared__ u64 s[NFFT];
    const int t = threadIdx.x;               // 0..63
    const size_t base = (size_t)blockIdx.x * NFFT;

    u64 v[16];

    // ---- Phase A: DFT16 over n1 (stride 64), twiddle W1024^(t*k1) ----
#pragma unroll
    for (int n1 = 0; n1 < 16; ++n1)
        v[n1] = pk(gre[base + 64 * n1 + t], gim[base + 64 * n1 + t]);
    dft16_inv(v);
    {
        const float ang = (TWO_PI / 1024.0f) * (float)t;
#pragma unroll
        for (int k1 = 1; k1 < 16; ++k1) {
            float sn, cs;
            __sincosf(ang * (float)k1, &sn, &cs);
            v[k1] = cmulc(v[k1], cs, sn);
        }
        const int hi = (t >> 4) << 8;
        const int lo = t & 15;
#pragma unroll
        for (int k1 = 0; k1 < 16; ++k1)
            s[hi | (k1 << 4) | (lo ^ ((k1 & 3) << 2))] = v[k1];
    }
    __syncthreads();

    // ---- Phase B: DFT16 over m (n2 = 4m+q), twiddle W64^(q*c) ----
    {
        const int k1 = t >> 2, q = t & 3;
#pragma unroll
        for (int m = 0; m < 16; ++m) {
            const int n2 = 4 * m + q;
            const int phys = ((n2 >> 4) << 8) | (k1 << 4) | ((n2 & 15) ^ ((k1 & 3) << 2));
            v[m] = s[phys];
        }
        dft16_inv(v);
        const float ang = (TWO_PI / 64.0f) * (float)q;
#pragma unroll
        for (int c = 1; c < 16; ++c) {
            float sn, cs;
            __sincosf(ang * (float)c, &sn, &cs);
            v[c] = cmulc(v[c], cs, sn);
        }
        __syncthreads();   // all reads of exchange-1 complete before reuse
#pragma unroll
        for (int c = 0; c < 16; ++c) {
            const int idx = k1 + 16 * c + 256 * q;
            s[idx ^ (q << 2)] = v[c];
        }
    }
    __syncthreads();

    // ---- Phase C: final radix-4 across q, coalesced stores ----
    {
        const u64 SC = 0x3A8000003A800000ULL;   // packed (1/1024, 1/1024)
#pragma unroll
        for (int jj = 0; jj < 4; ++jj) {
            const int p = t + 64 * jj;     // p = k1 + 16*c in [0,256)
            u64 u[4];
#pragma unroll
            for (int q = 0; q < 4; ++q) {
                const int idx = p + 256 * q;
                u[q] = s[idx ^ (q << 2)];
            }
            bfly4_inv(u);
#pragma unroll
            for (int d = 0; d < 4; ++d) {
                u64 y = pmul(u[d], SC);
                float yr, yi; upk(y, yr, yi);
                outr[base + p + 256 * d] = yr;
                outi[base + p + 256 * d] = yi;
            }
        }
    }
}

extern "C" void kernel_launch(void* const* d_in, const int* in_sizes, int n_in,
                              void* d_out, int out_size) {
    const float* re = (const float*)d_in[0];
    const float* im = (const float*)d_in[1];
    float* out = (float*)d_out;
    const int half = out_size / 2;           // y_real then y_imag, concatenated
    const int nrows = in_sizes[0] / NFFT;    // 32768
    ifft1024_kernel<<<nrows, 64>>>(re, im, out, out + half);
}

// round 10
// speedup vs baseline: 1.1401x; 1.0020x over previous
#include <cuda_runtime.h>

typedef unsigned long long u64;
#define NFFT 1024
#define TWO_PI 6.2831853071795864769f

// ---- packed f32x2 helpers (sm_103a) ----
__device__ __forceinline__ u64 pk(float x, float y) {
    u64 u; asm("mov.b64 %0,{%1,%2};" : "=l"(u) : "f"(x), "f"(y)); return u;
}
__device__ __forceinline__ void upk(u64 u, float& x, float& y) {
    asm("mov.b64 {%0,%1},%2;" : "=f"(x), "=f"(y) : "l"(u));
}
__device__ __forceinline__ u64 padd(u64 a, u64 b) {
    u64 d; asm("add.rn.f32x2 %0,%1,%2;" : "=l"(d) : "l"(a), "l"(b)); return d;
}
__device__ __forceinline__ u64 pmul(u64 a, u64 b) {
    u64 d; asm("mul.rn.f32x2 %0,%1,%2;" : "=l"(d) : "l"(a), "l"(b)); return d;
}
__device__ __forceinline__ u64 pfma(u64 a, u64 b, u64 c) {
    u64 d; asm("fma.rn.f32x2 %0,%1,%2,%3;" : "=l"(d) : "l"(a), "l"(b), "l"(c)); return d;
}
__device__ __forceinline__ u64 psub(u64 a, u64 b) {  // a - b
    const u64 NEG1 = 0xBF800000BF800000ULL;
    return pfma(b, NEG1, a);
}
__device__ __forceinline__ u64 cmulc(u64 a, float br, float bi) {
    float ar, ai; upk(a, ar, ai);
    return pk(fmaf(-ai, bi, ar * br), fmaf(ar, bi, ai * br));
}
__device__ __forceinline__ u64 muli(u64 a) {  // a * i
    float ar, ai; upk(a, ar, ai);
    return pk(-ai, ar);
}

// Inverse (sign = +i) radix-4 butterfly on packed complex values.
__device__ __forceinline__ void bfly4_inv(u64 v[4]) {
    u64 t0 = padd(v[0], v[2]);
    u64 t1 = psub(v[0], v[2]);
    u64 t2 = padd(v[1], v[3]);
    u64 t3 = psub(v[1], v[3]);
    v[0] = padd(t0, t2);
    v[2] = psub(t0, t2);
    u64 w = muli(t3);
    v[1] = padd(t1, w);
    v[3] = psub(t1, w);
}

// In-register inverse 16-point DFT, natural order in and out.
__device__ __forceinline__ void dft16_inv(u64 v[16]) {
    const float C  = 0.70710678118654752f;   // cos(pi/4)
    const float C1 = 0.92387953251128676f;   // cos(pi/8)
    const float S1 = 0.38268343236508977f;   // sin(pi/8)
    u64 a[16];  // a[k1*4 + n2]
#pragma unroll
    for (int n2 = 0; n2 < 4; ++n2) {
        u64 t[4] = { v[n2], v[n2 + 4], v[n2 + 8], v[n2 + 12] };
        bfly4_inv(t);
        a[0 + n2] = t[0]; a[4 + n2] = t[1]; a[8 + n2] = t[2]; a[12 + n2] = t[3];
    }
    a[4 + 1]  = cmulc(a[4 + 1],  C1,  S1);
    a[4 + 2]  = cmulc(a[4 + 2],  C,   C);
    a[4 + 3]  = cmulc(a[4 + 3],  S1,  C1);
    a[8 + 1]  = cmulc(a[8 + 1],  C,   C);
    a[8 + 2]  = muli (a[8 + 2]);
    a[8 + 3]  = cmulc(a[8 + 3], -C,   C);
    a[12 + 1] = cmulc(a[12 + 1],  S1,  C1);
    a[12 + 2] = cmulc(a[12 + 2], -C,   C);
    a[12 + 3] = cmulc(a[12 + 3], -C1, -S1);
#pragma unroll
    for (int k1 = 0; k1 < 4; ++k1) {
        u64 t[4] = { a[k1 * 4 + 0], a[k1 * 4 + 1], a[k1 * 4 + 2], a[k1 * 4 + 3] };
        bfly4_inv(t);
        v[k1] = t[0]; v[k1 + 4] = t[1]; v[k1 + 8] = t[2]; v[k1 + 12] = t[3];
    }
}

// Apply v[k] *= W^k for k=1..15 where W = (c1, s1), by incremental complex
// rotation: 1 sincos outside + 14 rotation steps (4 FFMA each) instead of
// 15 MUFU sincos pairs. Chained error ~15 ulp, far inside tolerance.
__device__ __forceinline__ void twiddle_chain(u64 v[16], float c1, float s1) {
    float cs = c1, sn = s1;
    v[1] = cmulc(v[1], cs, sn);
#pragma unroll
    for (int k = 2; k < 16; ++k) {
        float cn = fmaf(-sn, s1, cs * c1);
        float sx = fmaf( cs, s1, sn * c1);
        cs = cn; sn = sx;
        v[k] = cmulc(v[k], cs, sn);
    }
}

// 1024-pt inverse FFT, one row per 64-thread CTA (R9 structure), with
// twiddles generated by incremental rotation instead of per-k sincos.
__global__ void __launch_bounds__(64, 16)
ifft1024_kernel(const float* __restrict__ gre, const float* __restrict__ gim,
                float* __restrict__ outr, float* __restrict__ outi)
{
    __shared__ u64 s[NFFT];
    const int t = threadIdx.x;               // 0..63
    const size_t base = (size_t)blockIdx.x * NFFT;

    u64 v[16];

    // ---- Phase A: DFT16 over n1 (stride 64), twiddle W1024^(t*k1) ----
#pragma unroll
    for (int n1 = 0; n1 < 16; ++n1)
        v[n1] = pk(gre[base + 64 * n1 + t], gim[base + 64 * n1 + t]);
    dft16_inv(v);
    {
        float s1, c1;
        __sincosf((TWO_PI / 1024.0f) * (float)t, &s1, &c1);
        twiddle_chain(v, c1, s1);
        const int hi = (t >> 4) << 8;
        const int lo = t & 15;
#pragma unroll
        for (int k1 = 0; k1 < 16; ++k1)
            s[hi | (k1 << 4) | (lo ^ ((k1 & 3) << 2))] = v[k1];
    }
    __syncthreads();

    // ---- Phase B: DFT16 over m (n2 = 4m+q), twiddle W64^(q*c) ----
    {
        const int k1 = t >> 2, q = t & 3;
#pragma unroll
        for (int m = 0; m < 16; ++m) {
            const int n2 = 4 * m + q;
            const int phys = ((n2 >> 4) << 8) | (k1 << 4) | ((n2 & 15) ^ ((k1 & 3) << 2));
            v[m] = s[phys];
        }
        dft16_inv(v);
        {
            float s1, c1;
            __sincosf((TWO_PI / 64.0f) * (float)q, &s1, &c1);
            twiddle_chain(v, c1, s1);
        }
        __syncthreads();   // all reads of exchange-1 complete before reuse
#pragma unroll
        for (int c = 0; c < 16; ++c) {
            const int idx = k1 + 16 * c + 256 * q;
            s[idx ^ (q << 2)] = v[c];
        }
    }
    __syncthreads();

    // ---- Phase C: final radix-4 across q, coalesced stores ----
    {
        const u64 SC = 0x3A8000003A800000ULL;   // packed (1/1024, 1/1024)
#pragma unroll
        for (int jj = 0; jj < 4; ++jj) {
            const int p = t + 64 * jj;     // p = k1 + 16*c in [0,256)
            u64 u[4];
#pragma unroll
            for (int q = 0; q < 4; ++q) {
                const int idx = p + 256 * q;
                u[q] = s[idx ^ (q << 2)];
            }
            bfly4_inv(u);
#pragma unroll
            for (int d = 0; d < 4; ++d) {
                u64 y = pmul(u[d], SC);
                float yr, yi; upk(y, yr, yi);
                outr[base + p + 256 * d] = yr;
                outi[base + p + 256 * d] = yi;
            }
        }
    }
}

extern "C" void kernel_launch(void* const* d_in, const int* in_sizes, int n_in,
                              void* d_out, int out_size) {
    const float* re = (const float*)d_in[0];
    const float* im = (const float*)d_in[1];
    float* out = (float*)d_out;
    const int half = out_size / 2;           // y_real then y_imag, concatenated
    const int nrows = in_sizes[0] / NFFT;    // 32768
    ifft1024_kernel<<<nrows, 64>>>(re, im, out, out + half);
}

// round 11
// speedup vs baseline: 1.1410x; 1.0008x over previous
#include <cuda_runtime.h>

typedef unsigned long long u64;
#define NFFT 1024
#define TWO_PI 6.2831853071795864769f

// ---- packed f32x2 helpers (sm_103a) ----
__device__ __forceinline__ u64 pk(float x, float y) {
    u64 u; asm("mov.b64 %0,{%1,%2};" : "=l"(u) : "f"(x), "f"(y)); return u;
}
__device__ __forceinline__ void upk(u64 u, float& x, float& y) {
    asm("mov.b64 {%0,%1},%2;" : "=f"(x), "=f"(y) : "l"(u));
}
__device__ __forceinline__ u64 padd(u64 a, u64 b) {
    u64 d; asm("add.rn.f32x2 %0,%1,%2;" : "=l"(d) : "l"(a), "l"(b)); return d;
}
__device__ __forceinline__ u64 pmul(u64 a, u64 b) {
    u64 d; asm("mul.rn.f32x2 %0,%1,%2;" : "=l"(d) : "l"(a), "l"(b)); return d;
}
__device__ __forceinline__ u64 pfma(u64 a, u64 b, u64 c) {
    u64 d; asm("fma.rn.f32x2 %0,%1,%2,%3;" : "=l"(d) : "l"(a), "l"(b), "l"(c)); return d;
}
__device__ __forceinline__ u64 psub(u64 a, u64 b) {  // a - b
    const u64 NEG1 = 0xBF800000BF800000ULL;
    return pfma(b, NEG1, a);
}
__device__ __forceinline__ u64 cmulc(u64 a, float br, float bi) {
    float ar, ai; upk(a, ar, ai);
    return pk(fmaf(-ai, bi, ar * br), fmaf(ar, bi, ai * br));
}
__device__ __forceinline__ u64 muli(u64 a) {  // a * i
    float ar, ai; upk(a, ar, ai);
    return pk(-ai, ar);
}

// Inverse (sign = +i) radix-4 butterfly on packed complex values.
__device__ __forceinline__ void bfly4_inv(u64 v[4]) {
    u64 t0 = padd(v[0], v[2]);
    u64 t1 = psub(v[0], v[2]);
    u64 t2 = padd(v[1], v[3]);
    u64 t3 = psub(v[1], v[3]);
    v[0] = padd(t0, t2);
    v[2] = psub(t0, t2);
    u64 w = muli(t3);
    v[1] = padd(t1, w);
    v[3] = psub(t1, w);
}

// In-register inverse 16-point DFT, natural order in and out.
__device__ __forceinline__ void dft16_inv(u64 v[16]) {
    const float C  = 0.70710678118654752f;   // cos(pi/4)
    const float C1 = 0.92387953251128676f;   // cos(pi/8)
    const float S1 = 0.38268343236508977f;   // sin(pi/8)
    u64 a[16];  // a[k1*4 + n2]
#pragma unroll
    for (int n2 = 0; n2 < 4; ++n2) {
        u64 t[4] = { v[n2], v[n2 + 4], v[n2 + 8], v[n2 + 12] };
        bfly4_inv(t);
        a[0 + n2] = t[0]; a[4 + n2] = t[1]; a[8 + n2] = t[2]; a[12 + n2] = t[3];
    }
    a[4 + 1]  = cmulc(a[4 + 1],  C1,  S1);
    a[4 + 2]  = cmulc(a[4 + 2],  C,   C);
    a[4 + 3]  = cmulc(a[4 + 3],  S1,  C1);
    a[8 + 1]  = cmulc(a[8 + 1],  C,   C);
    a[8 + 2]  = muli (a[8 + 2]);
    a[8 + 3]  = cmulc(a[8 + 3], -C,   C);
    a[12 + 1] = cmulc(a[12 + 1],  S1,  C1);
    a[12 + 2] = cmulc(a[12 + 2], -C,   C);
    a[12 + 3] = cmulc(a[12 + 3], -C1, -S1);
#pragma unroll
    for (int k1 = 0; k1 < 4; ++k1) {
        u64 t[4] = { a[k1 * 4 + 0], a[k1 * 4 + 1], a[k1 * 4 + 2], a[k1 * 4 + 3] };
        bfly4_inv(t);
        v[k1] = t[0]; v[k1 + 4] = t[1]; v[k1 + 8] = t[2]; v[k1 + 12] = t[3];
    }
}

// v[k] *= g * W^k, k=1..15, W=(c1,s1), g = optional uniform gain folded into
// the seeds (rotation steps by the UNSCALED (c1,s1) preserve the gain).
// Dual-seeded from W^1 and W^8 to halve the serial dependency depth.
__device__ __forceinline__ void twiddle_chain_dual(u64 v[16],
                                                   float c1, float s1,
                                                   float c8, float s8,
                                                   float g) {
    // chain 1: k = 1..7, seed g*W^1
    float cs = g * c1, sn = g * s1;
    v[1] = cmulc(v[1], cs, sn);
#pragma unroll
    for (int k = 2; k < 8; ++k) {
        float cn = fmaf(-sn, s1, cs * c1);
        float sx = fmaf( cs, s1, sn * c1);
        cs = cn; sn = sx;
        v[k] = cmulc(v[k], cs, sn);
    }
    // chain 2: k = 8..15, seed g*W^8
    cs = g * c8; sn = g * s8;
    v[8] = cmulc(v[8], cs, sn);
#pragma unroll
    for (int k = 9; k < 16; ++k) {
        float cn = fmaf(-sn, s1, cs * c1);
        float sx = fmaf( cs, s1, sn * c1);
        cs = cn; sn = sx;
        v[k] = cmulc(v[k], cs, sn);
    }
}

// 1024-pt inverse FFT, one row per 64-thread CTA. Twiddles by dual-seeded
// incremental rotation; 1/1024 normalization folded into Phase B twiddles.
__global__ void __launch_bounds__(64, 16)
ifft1024_kernel(const float* __restrict__ gre, const float* __restrict__ gim,
                float* __restrict__ outr, float* __restrict__ outi)
{
    __shared__ u64 s[NFFT];
    const int t = threadIdx.x;               // 0..63
    const size_t base = (size_t)blockIdx.x * NFFT;

    u64 v[16];

    // ---- Phase A: DFT16 over n1 (stride 64), twiddle W1024^(t*k1) ----
#pragma unroll
    for (int n1 = 0; n1 < 16; ++n1)
        v[n1] = pk(gre[base + 64 * n1 + t], gim[base + 64 * n1 + t]);
    dft16_inv(v);
    {
        const float th = (TWO_PI / 1024.0f) * (float)t;
        float s1, c1, s8, c8;
        __sincosf(th, &s1, &c1);
        __sincosf(8.0f * th, &s8, &c8);
        twiddle_chain_dual(v, c1, s1, c8, s8, 1.0f);
        const int hi = (t >> 4) << 8;
        const int lo = t & 15;
#pragma unroll
        for (int k1 = 0; k1 < 16; ++k1)
            s[hi | (k1 << 4) | (lo ^ ((k1 & 3) << 2))] = v[k1];
    }
    __syncthreads();

    // ---- Phase B: DFT16 over m (n2 = 4m+q), twiddle SC * W64^(q*c) ----
    {
        const int k1 = t >> 2, q = t & 3;
#pragma unroll
        for (int m = 0; m < 16; ++m) {
            const int n2 = 4 * m + q;
            const int phys = ((n2 >> 4) << 8) | (k1 << 4) | ((n2 & 15) ^ ((k1 & 3) << 2));
            v[m] = s[phys];
        }
        dft16_inv(v);
        {
            const float SCALE = 1.0f / 1024.0f;   // exact power of 2
            const float ph = (TWO_PI / 64.0f) * (float)q;
            float s1, c1, s8, c8;
            __sincosf(ph, &s1, &c1);
            __sincosf(8.0f * ph, &s8, &c8);
            const u64 SCpk = 0x3A8000003A800000ULL;  // packed (1/1024, 1/1024)
            v[0] = pmul(v[0], SCpk);
            twiddle_chain_dual(v, c1, s1, c8, s8, SCALE);
        }
        __syncthreads();   // all reads of exchange-1 complete before reuse
#pragma unroll
        for (int c = 0; c < 16; ++c) {
            const int idx = k1 + 16 * c + 256 * q;
            s[idx ^ (q << 2)] = v[c];
        }
    }
    __syncthreads();

    // ---- Phase C: final radix-4 across q, coalesced stores (pre-scaled) ----
    {
#pragma unroll
        for (int jj = 0; jj < 4; ++jj) {
            const int p = t + 64 * jj;     // p = k1 + 16*c in [0,256)
            u64 u[4];
#pragma unroll
            for (int q = 0; q < 4; ++q) {
                const int idx = p + 256 * q;
                u[q] = s[idx ^ (q << 2)];
            }
            bfly4_inv(u);
#pragma unroll
            for (int d = 0; d < 4; ++d) {
                float yr, yi; upk(u[d], yr, yi);
                outr[base + p + 256 * d] = yr;
                outi[base + p + 256 * d] = yi;
            }
        }
    }
}

extern "C" void kernel_launch(void* const* d_in, const int* in_sizes, int n_in,
                              void* d_out, int out_size) {
    const float* re = (const float*)d_in[0];
    const float* im = (const float*)d_in[1];
    float* out = (float*)d_out;
    const int half = out_size / 2;           // y_real then y_imag, concatenated
    const int nrows = in_sizes[0] / NFFT;    // 32768
    ifft1024_kernel<<<nrows, 64>>>(re, im, out, out + half);
}